// round 4
// baseline (speedup 1.0000x reference)
#include <cuda_runtime.h>
#include <math.h>

#define BG 256
#define TT 64
#define PP 10
#define DD 128
#define HH 64
#define BT (BG*TT)   // 16384
#define GPB 8        // lstm games per block

typedef unsigned long long u64;

// ---- device scratch (allocation-free) ----
__device__ float g_z[BT*PP*64];            // SGCN output z  [bt][p][64]
__device__ float g_gih[(size_t)BT*PP*256]; // gates_ih+bias  [bt][p][256]
__device__ float g_WbT[2*32*256];          // base W  [s][col][k]
__device__ float g_WdT[2*2*32*224];        // deep W  [s][layer][col][k]

// ---- packed fp32x2 helpers (sm_100+ double-rate fp32) ----
__device__ __forceinline__ void ffma2(u64& d, u64 a, u64 b){
    asm("fma.rn.f32x2 %0, %1, %2, %0;" : "+l"(d) : "l"(a), "l"(b));
}
__device__ __forceinline__ float hadd2(u64 v){
    float lo, hi; asm("mov.b64 {%0,%1}, %2;" : "=f"(lo), "=f"(hi) : "l"(v));
    return lo + hi;
}

// fast activations
__device__ __forceinline__ float tanh_mufu(float x){
    float y; asm("tanh.approx.f32 %0, %1;" : "=f"(y) : "f"(x)); return y;
}
__device__ __forceinline__ float sigmoid_fast(float v){
    return __fdividef(1.0f, 1.0f + __expf(-v));
}
__device__ __forceinline__ float tanh_fast(float v){
    return __fdividef(2.0f, 1.0f + __expf(-2.0f*v)) - 1.0f;
}

// ------------------------------------------------------------------
// Kernel 0: SGCN weight transpose to k-major [col][k]
// ------------------------------------------------------------------
__global__ void transform_weights(
    const float* __restrict__ Wpb, const float* __restrict__ Wnb,
    const float* __restrict__ Wpd, const float* __restrict__ Wnd)
{
    int idx = blockIdx.x*blockDim.x + threadIdx.x;
    if (idx < 2*32*256){
        int s = idx / 8192, rem = idx - s*8192;
        int col = rem >> 8, k = rem & 255;
        g_WbT[idx] = (s ? Wnb : Wpb)[k*32 + col];
    } else if (idx < 2*32*256 + 2*2*32*224){
        int i2 = idx - 2*32*256;
        int s = i2 / 14336; int rem = i2 - s*14336;
        int layer = rem / 7168; rem -= layer*7168;
        int col = rem / 224; int k = rem - col*224;
        g_WdT[((s*2 + layer)*32 + col)*224 + k] =
            (s ? Wnd : Wpd)[layer*224*32 + k*32 + col];
    }
}

// ------------------------------------------------------------------
// Kernel 1: SGCN. One block per (b,t). 256 threads. FFMA2 matmuls.
// ------------------------------------------------------------------
__global__ __launch_bounds__(256) void sgcn_kernel(
    const float* __restrict__ x,
    const float* __restrict__ Apos, const float* __restrict__ Aneg,
    const float* __restrict__ bpb,  const float* __restrict__ bnb,
    const float* __restrict__ bpd,  const float* __restrict__ bnd)
{
    __shared__ float xs[PP*DD];        // 1280
    __shared__ float Asm[2][PP*PP];
    __shared__ float rs[2][PP];
    __shared__ float aggx[2*PP*DD];    // 2560
    __shared__ float cat[6*PP*32];     // [0..3]=deep aggs, [4]=h_pos, [5]=h_neg
    __shared__ float part[4*2*PP*32];

    const int bt  = blockIdx.x;
    const int tid = threadIdx.x;

    {   // x tile (float4)
        const float4* x4 = (const float4*)(x + (size_t)bt*PP*DD);
        float4* xs4 = (float4*)xs;
        for (int i = tid; i < PP*DD/4; i += 256) xs4[i] = x4[i];
    }
    if (tid < 200){
        int s = tid/100, idx = tid - s*100;
        Asm[s][idx] = (s ? Aneg : Apos)[(size_t)bt*100 + idx];
    }
    __syncthreads();
    if (tid < 20){
        int s = tid/10, r = tid - s*10;
        float sum = 0.f;
        #pragma unroll
        for (int j=0;j<10;j++) sum += Asm[s][r*10+j];
        rs[s][r] = __fdividef(1.0f, sum + 1e-8f);
    }
    __syncthreads();
    if (tid < 200){
        int s = tid/100, idx = tid - s*100;
        Asm[s][idx] *= rs[s][idx/10];
    }
    __syncthreads();

    // aggx[s][r][:] = An_s[r] @ x
    {
        float4* ag4 = (float4*)aggx;
        const float4* xs4 = (const float4*)xs;
        for (int o = tid; o < 2*PP*32; o += 256){
            int s = o / 320; int rem = o - s*320;
            int r = rem >> 5; int d4 = rem & 31;
            float4 sum = make_float4(0.f,0.f,0.f,0.f);
            #pragma unroll
            for (int j=0;j<10;j++){
                float a = Asm[s][r*10+j];
                float4 xv = xs4[j*32 + d4];
                sum.x += a*xv.x; sum.y += a*xv.y; sum.z += a*xv.z; sum.w += a*xv.w;
            }
            ag4[o] = sum;
        }
    }
    __syncthreads();

    // base matmul: h_s = tanh(cat([agg_s, x]) @ W_s_base + b), K=256, FFMA2
    {
        const int col = tid & 31;
        const int s   = (tid>>5) & 1;
        const int q   = tid>>6;          // 0..3 -> 64 k each
        const float* Wt = g_WbT + ((size_t)s*32 + col)*256 + q*64;
        const float* src = (q < 2) ? (aggx + s*1280 + q*64) : (xs + (q-2)*64);
        u64 accP[10];
        #pragma unroll
        for (int r=0;r<10;r++) accP[r]=0ull;
        #pragma unroll 4
        for (int kk=0;kk<64;kk+=4){
            ulonglong2 w2 = *(const ulonglong2*)&Wt[kk];
            #pragma unroll
            for (int r=0;r<10;r++){
                ulonglong2 a2 = *(const ulonglong2*)&src[r*128 + kk];
                ffma2(accP[r], a2.x, w2.x);
                ffma2(accP[r], a2.y, w2.y);
            }
        }
        #pragma unroll
        for (int r=0;r<10;r++) part[((q*2+s)*10+r)*32+col] = hadd2(accP[r]);
    }
    __syncthreads();
    for (int o=tid; o<640; o+=256){
        int s = o/320, rem = o - s*320, r = rem>>5, col = rem&31;
        float v = (s ? bnb : bpb)[col];
        #pragma unroll
        for (int q=0;q<4;q++) v += part[((q*2+s)*10+r)*32+col];
        cat[(4+s)*320 + r*32 + col] = tanh_mufu(v);
    }
    __syncthreads();

    // two deep layers, K=224, FFMA2
    for (int layer=0; layer<2; layer++){
        for (int o=tid; o<320; o+=256){
            int m = o/80, rem = o - m*80, r = rem>>3, c4 = (rem&7)*4;
            int as = m>>1, hsn = m&1;
            float4 sum = make_float4(0.f,0.f,0.f,0.f);
            #pragma unroll
            for (int j=0;j<10;j++){
                float a = Asm[as][r*10+j];
                float4 h = *(const float4*)&cat[(4+hsn)*320 + j*32 + c4];
                sum.x += a*h.x; sum.y += a*h.y; sum.z += a*h.z; sum.w += a*h.w;
            }
            *(float4*)&cat[m*320 + r*32 + c4] = sum;
        }
        __syncthreads();
        {
            const int col = tid & 31;
            const int s   = (tid>>5) & 1;
            const int q   = tid>>6;      // 0..3 -> 56 k each
            const float* Wt = g_WdT + (((size_t)(s*2+layer))*32 + col)*224 + q*56;
            u64 accP[10];
            #pragma unroll
            for (int r=0;r<10;r++) accP[r]=0ull;
            #pragma unroll 2
            for (int kk=0;kk<56;kk+=4){
                int k = q*56 + kk;
                int blk = k>>5, ko = k&31;
                const float* src = cat + ((blk<6) ? blk : (4+s))*320 + ko;
                ulonglong2 w2 = *(const ulonglong2*)&Wt[kk];
                #pragma unroll
                for (int r=0;r<10;r++){
                    ulonglong2 a2 = *(const ulonglong2*)&src[r*32];
                    ffma2(accP[r], a2.x, w2.x);
                    ffma2(accP[r], a2.y, w2.y);
                }
            }
            #pragma unroll
            for (int r=0;r<10;r++) part[((q*2+s)*10+r)*32+col] = hadd2(accP[r]);
        }
        __syncthreads();
        for (int o=tid; o<640; o+=256){
            int s = o/320, rem = o - s*320, r = rem>>5, col = rem&31;
            float v = (s ? bnd : bpd)[layer*32+col];
            #pragma unroll
            for (int q=0;q<4;q++) v += part[((q*2+s)*10+r)*32+col];
            cat[(4+s)*320 + r*32 + col] = tanh_mufu(v);
        }
        __syncthreads();
    }

    // write z = cat([h_pos, h_neg], -1)
    float* zo = g_z + (size_t)bt*PP*64;
    for (int o=tid; o<640; o+=256){
        int r = o>>6, c = o&63, s = c>>5, cc = c&31;
        zo[o] = cat[(4+s)*320 + r*32 + cc];
    }
}

// ------------------------------------------------------------------
// Kernel 2: gates_ih = z @ W_ih^T + (b_ih + b_hh)
// 16-row tiles, thread = 4 rows x 4 gates, FFMA2 over k. W_ih native [g][i].
// ------------------------------------------------------------------
__global__ __launch_bounds__(256) void gih_kernel(
    const float* __restrict__ Wih,
    const float* __restrict__ bih, const float* __restrict__ bhh)
{
    __shared__ float zs[16*64];

    const int p   = blockIdx.y;
    const int r0  = blockIdx.x * 16;
    const int tid = threadIdx.x;

    {   // one float4 per thread
        int rr = tid >> 4, d4 = tid & 15;
        ((float4*)zs)[tid] = *(const float4*)&g_z[((size_t)(r0+rr)*10 + p)*64 + d4*4];
    }
    __syncthreads();

    const int g0  = (tid & 63) * 4;   // 4 consecutive gates
    const int rr0 = (tid >> 6) * 4;   // 4 rows
    const float* W = Wih + (size_t)p*16384 + g0*64;  // 4 rows of 64, contiguous

    u64 accP[4][4];
    #pragma unroll
    for (int r=0;r<4;r++){
        #pragma unroll
        for (int g=0;g<4;g++) accP[r][g]=0ull;
    }

    #pragma unroll 4
    for (int i0=0; i0<64; i0+=4){
        ulonglong2 w0 = *(const ulonglong2*)&W[0*64 + i0];
        ulonglong2 w1 = *(const ulonglong2*)&W[1*64 + i0];
        ulonglong2 w2 = *(const ulonglong2*)&W[2*64 + i0];
        ulonglong2 w3 = *(const ulonglong2*)&W[3*64 + i0];
        #pragma unroll
        for (int r=0;r<4;r++){
            ulonglong2 z2 = *(const ulonglong2*)&zs[(rr0+r)*64 + i0];
            ffma2(accP[r][0], z2.x, w0.x); ffma2(accP[r][0], z2.y, w0.y);
            ffma2(accP[r][1], z2.x, w1.x); ffma2(accP[r][1], z2.y, w1.y);
            ffma2(accP[r][2], z2.x, w2.x); ffma2(accP[r][2], z2.y, w2.y);
            ffma2(accP[r][3], z2.x, w3.x); ffma2(accP[r][3], z2.y, w3.y);
        }
    }

    float b0 = bih[p*256+g0+0] + bhh[p*256+g0+0];
    float b1 = bih[p*256+g0+1] + bhh[p*256+g0+1];
    float b2 = bih[p*256+g0+2] + bhh[p*256+g0+2];
    float b3 = bih[p*256+g0+3] + bhh[p*256+g0+3];

    #pragma unroll
    for (int r=0;r<4;r++){
        size_t bt = (size_t)(r0 + rr0 + r);
        float4 o = make_float4(hadd2(accP[r][0])+b0, hadd2(accP[r][1])+b1,
                               hadd2(accP[r][2])+b2, hadd2(accP[r][3])+b3);
        *(float4*)&g_gih[(bt*10 + p)*256 + g0] = o;
    }
}

// ------------------------------------------------------------------
// Kernel 3: LSTM recurrence. One block per (p, 8-game chunk).
// Thread owns gate gt (packed W_hh row in regs) for 8 games. FFMA2.
// grid = PP * (BG/GPB) = 320 blocks.
// ------------------------------------------------------------------
__global__ __launch_bounds__(256) void lstm_kernel(
    const float* __restrict__ Whh, float* __restrict__ out)
{
    __shared__ float hs[GPB][64];
    __shared__ float gsm[GPB][256];

    const int p     = blockIdx.x >> 5;        // 0..9
    const int chunk = blockIdx.x & 31;        // 0..31
    const int b0    = chunk*GPB;
    const int gt    = threadIdx.x;
    const int gm    = gt >> 6;    // activation: base game 0..3 (and +4)
    const int j     = gt & 63;

    u64 wp[32];                   // packed (w2k, w2k+1)
    {
        const ulonglong2* Wp2 = (const ulonglong2*)(Whh + (size_t)p*16384 + gt*64);
        #pragma unroll
        for (int i=0;i<16;i++){
            ulonglong2 v = Wp2[i];
            wp[2*i] = v.x; wp[2*i+1] = v.y;
        }
    }
    #pragma unroll
    for (int g=gm; g<GPB; g+=4) hs[g][j] = 0.f;
    float creg0 = 0.f, creg1 = 0.f;
    __syncthreads();

    // prefetch t=0 gates
    float pf[GPB];
    #pragma unroll
    for (int g=0; g<GPB; g++)
        pf[g] = g_gih[((size_t)(b0+g)*64*10 + p)*256 + gt];

    for (int t=0; t<TT; t++){
        u64 accP[GPB];
        #pragma unroll
        for (int g=0; g<GPB; g++) accP[g]=0ull;

        #pragma unroll
        for (int k0=0;k0<64;k0+=4){
            u64 wA = wp[k0>>1], wB = wp[(k0>>1)+1];
            #pragma unroll
            for (int g=0; g<GPB; g++){
                ulonglong2 h2 = *(const ulonglong2*)&hs[g][k0];
                ffma2(accP[g], h2.x, wA);
                ffma2(accP[g], h2.y, wB);
            }
        }
        // prefetch next step's gates while accumulation results settle
        float pfn[GPB];
        if (t < TT-1){
            #pragma unroll
            for (int g=0; g<GPB; g++)
                pfn[g] = g_gih[(((size_t)(b0+g)*64 + t+1)*10 + p)*256 + gt];
        }
        #pragma unroll
        for (int g=0; g<GPB; g++) gsm[g][gt] = pf[g] + hadd2(accP[g]);
        #pragma unroll
        for (int g=0; g<GPB; g++) pf[g] = pfn[g];
        __syncthreads();
        {
            // item 0: game gm
            float ig = sigmoid_fast(gsm[gm][j]);
            float fg = sigmoid_fast(gsm[gm][64+j]);
            float gg = tanh_fast   (gsm[gm][128+j]);
            float og = sigmoid_fast(gsm[gm][192+j]);
            creg0 = fg*creg0 + ig*gg;
            float h = og*tanh_fast(creg0);
            hs[gm][j] = h;
            out[(((size_t)(b0+gm)*64 + t)*10 + p)*64 + j] = h;
            // item 1: game gm+4
            int g2 = gm+4;
            ig = sigmoid_fast(gsm[g2][j]);
            fg = sigmoid_fast(gsm[g2][64+j]);
            gg = tanh_fast   (gsm[g2][128+j]);
            og = sigmoid_fast(gsm[g2][192+j]);
            creg1 = fg*creg1 + ig*gg;
            h = og*tanh_fast(creg1);
            hs[g2][j] = h;
            out[(((size_t)(b0+g2)*64 + t)*10 + p)*64 + j] = h;
        }
        __syncthreads();
    }
}

// ------------------------------------------------------------------
extern "C" void kernel_launch(void* const* d_in, const int* in_sizes, int n_in,
                              void* d_out, int out_size)
{
    const float* x    = (const float*)d_in[0];
    const float* Apos = (const float*)d_in[1];
    const float* Aneg = (const float*)d_in[2];
    const float* Wpb  = (const float*)d_in[3];
    const float* bpb  = (const float*)d_in[4];
    const float* Wnb  = (const float*)d_in[5];
    const float* bnb  = (const float*)d_in[6];
    const float* Wpd  = (const float*)d_in[7];
    const float* bpd  = (const float*)d_in[8];
    const float* Wnd  = (const float*)d_in[9];
    const float* bnd  = (const float*)d_in[10];
    const float* Wih  = (const float*)d_in[11];
    const float* Whh  = (const float*)d_in[12];
    const float* bih  = (const float*)d_in[13];
    const float* bhh  = (const float*)d_in[14];
    float* out = (float*)d_out;

    transform_weights<<<(2*32*256 + 2*2*32*224 + 255)/256, 256>>>(Wpb, Wnb, Wpd, Wnd);

    sgcn_kernel<<<BT, 256>>>(x, Apos, Aneg, bpb, bnb, bpd, bnd);

    dim3 gg(BT/16, PP);
    gih_kernel<<<gg, 256>>>(Wih, bih, bhh);

    lstm_kernel<<<PP*(BG/GPB), 256>>>(Whh, out);   // 320 blocks
}

// round 5
// speedup vs baseline: 1.9360x; 1.9360x over previous
#include <cuda_runtime.h>
#include <math.h>

#define BG 256
#define TT 64
#define PP 10
#define DD 128
#define HH 64
#define BT (BG*TT)   // 16384

typedef unsigned long long u64;

// ---- device scratch (allocation-free) ----
__device__ float g_z[BT*PP*64];            // SGCN output z  [bt][p][64]
__device__ float g_gih[(size_t)BT*PP*256]; // gates_ih+bias  [bt][p][256]
// k-quad interleaved weights: float4 = (W[4kq..4kq+3][col]) ; lane dim = col
__device__ float4 g_WbQ[2*64*32];          // base [s][kq][col]
__device__ float4 g_WdQ[2*2*56*32];        // deep [s][layer][kq][col]
__device__ float4 g_WihQ[PP*16*256];       // lstm-ih [p][iq][g]

// ---- packed fp32x2 helpers ----
__device__ __forceinline__ void ffma2(u64& d, u64 a, u64 b){
    asm("fma.rn.f32x2 %0, %1, %2, %0;" : "+l"(d) : "l"(a), "l"(b));
}
__device__ __forceinline__ float hadd2(u64 v){
    float lo, hi; asm("mov.b64 {%0,%1}, %2;" : "=f"(lo), "=f"(hi) : "l"(v));
    return lo + hi;
}

// fast activations
__device__ __forceinline__ float tanh_mufu(float x){
    float y; asm("tanh.approx.f32 %0, %1;" : "=f"(y) : "f"(x)); return y;
}
__device__ __forceinline__ float sigmoid_fast(float v){
    return __fdividef(1.0f, 1.0f + __expf(-v));
}
__device__ __forceinline__ float tanh_fast(float v){
    return __fdividef(2.0f, 1.0f + __expf(-2.0f*v)) - 1.0f;
}

// ------------------------------------------------------------------
// Kernel 0: weight re-layout (k-quad interleave, col-coalesced)
// ------------------------------------------------------------------
__global__ void transform_weights(
    const float* __restrict__ Wpb, const float* __restrict__ Wnb,
    const float* __restrict__ Wpd, const float* __restrict__ Wnd,
    const float* __restrict__ Wih)
{
    int idx = blockIdx.x*blockDim.x + threadIdx.x;
    if (idx < 2*64*32){
        int s = idx / 2048, rem = idx - s*2048;
        int kq = rem >> 5, col = rem & 31;
        const float* W = s ? Wnb : Wpb;          // [256][32]
        g_WbQ[idx] = make_float4(W[(4*kq+0)*32+col], W[(4*kq+1)*32+col],
                                 W[(4*kq+2)*32+col], W[(4*kq+3)*32+col]);
    } else if (idx < 2*64*32 + 2*2*56*32){
        int i2 = idx - 2*64*32;
        int s = i2 / 3584; int rem = i2 - s*3584;
        int layer = rem / 1792; rem -= layer*1792;
        int kq = rem >> 5, col = rem & 31;
        const float* W = (s ? Wnd : Wpd) + layer*224*32;   // [224][32]
        g_WdQ[i2] = make_float4(W[(4*kq+0)*32+col], W[(4*kq+1)*32+col],
                                W[(4*kq+2)*32+col], W[(4*kq+3)*32+col]);
    } else if (idx < 2*64*32 + 2*2*56*32 + PP*16*256){
        int i3 = idx - (2*64*32 + 2*2*56*32);
        int p = i3 / 4096; int rem = i3 - p*4096;
        int iq = rem >> 8, g = rem & 255;
        const float* W = Wih + (size_t)p*16384 + g*64;     // row g, 64 i
        g_WihQ[i3] = make_float4(W[4*iq+0], W[4*iq+1], W[4*iq+2], W[4*iq+3]);
    }
}

// ------------------------------------------------------------------
// Kernel 1: SGCN. One block per (b,t). 256 threads. FFMA2 + coalesced W.
// ------------------------------------------------------------------
__global__ __launch_bounds__(256) void sgcn_kernel(
    const float* __restrict__ x,
    const float* __restrict__ Apos, const float* __restrict__ Aneg,
    const float* __restrict__ bpb,  const float* __restrict__ bnb,
    const float* __restrict__ bpd,  const float* __restrict__ bnd)
{
    __shared__ __align__(16) float xs[PP*DD];
    __shared__ float Asm[2][PP*PP];
    __shared__ float rs[2][PP];
    __shared__ __align__(16) float aggx[2*PP*DD];
    __shared__ __align__(16) float cat[6*PP*32];   // [0..3]=aggs, [4]=h_pos, [5]=h_neg
    __shared__ float part[4*2*PP*32];

    const int bt  = blockIdx.x;
    const int tid = threadIdx.x;

    {   // x tile
        const float4* x4 = (const float4*)(x + (size_t)bt*PP*DD);
        float4* xs4 = (float4*)xs;
        for (int i = tid; i < PP*DD/4; i += 256) xs4[i] = x4[i];
    }
    if (tid < 200){
        int s = tid/100, idx = tid - s*100;
        Asm[s][idx] = (s ? Aneg : Apos)[(size_t)bt*100 + idx];
    }
    __syncthreads();
    if (tid < 20){
        int s = tid/10, r = tid - s*10;
        float sum = 0.f;
        #pragma unroll
        for (int j=0;j<10;j++) sum += Asm[s][r*10+j];
        rs[s][r] = __fdividef(1.0f, sum + 1e-8f);
    }
    __syncthreads();
    if (tid < 200){
        int s = tid/100, idx = tid - s*100;
        Asm[s][idx] *= rs[s][idx/10];
    }
    __syncthreads();

    // aggx[s][r][:] = An_s[r] @ x
    {
        float4* ag4 = (float4*)aggx;
        const float4* xs4 = (const float4*)xs;
        for (int o = tid; o < 2*PP*32; o += 256){
            int s = o / 320; int rem = o - s*320;
            int r = rem >> 5; int d4 = rem & 31;
            float4 sum = make_float4(0.f,0.f,0.f,0.f);
            #pragma unroll
            for (int j=0;j<10;j++){
                float a = Asm[s][r*10+j];
                float4 xv = xs4[j*32 + d4];
                sum.x += a*xv.x; sum.y += a*xv.y; sum.z += a*xv.z; sum.w += a*xv.w;
            }
            ag4[o] = sum;
        }
    }
    __syncthreads();

    // base matmul: K=256, FFMA2, weights col-coalesced k-quads
    {
        const int col = tid & 31;
        const int s   = (tid>>5) & 1;
        const int q   = tid>>6;          // 0..3 -> 64 k (16 quads) each
        const ulonglong2* Wq = (const ulonglong2*)g_WbQ + (s*64 + q*16)*32 + col;
        const float* src = (q < 2) ? (aggx + s*1280 + q*64) : (xs + (q-2)*64);
        u64 accP[10];
        #pragma unroll
        for (int r=0;r<10;r++) accP[r]=0ull;
        #pragma unroll 4
        for (int kq=0;kq<16;kq++){
            ulonglong2 w = Wq[kq*32];
            #pragma unroll
            for (int r=0;r<10;r++){
                ulonglong2 a = *(const ulonglong2*)&src[r*128 + kq*4];
                ffma2(accP[r], a.x, w.x);
                ffma2(accP[r], a.y, w.y);
            }
        }
        #pragma unroll
        for (int r=0;r<10;r++) part[((q*2+s)*10+r)*32+col] = hadd2(accP[r]);
    }
    __syncthreads();
    for (int o=tid; o<640; o+=256){
        int s = o/320, rem = o - s*320, r = rem>>5, col = rem&31;
        float v = (s ? bnb : bpb)[col];
        #pragma unroll
        for (int q=0;q<4;q++) v += part[((q*2+s)*10+r)*32+col];
        cat[(4+s)*320 + r*32 + col] = tanh_mufu(v);
    }
    __syncthreads();

    // two deep layers, K=224, FFMA2
    for (int layer=0; layer<2; layer++){
        for (int o=tid; o<320; o+=256){
            int m = o/80, rem = o - m*80, r = rem>>3, c4 = (rem&7)*4;
            int as = m>>1, hsn = m&1;
            float4 sum = make_float4(0.f,0.f,0.f,0.f);
            #pragma unroll
            for (int j=0;j<10;j++){
                float a = Asm[as][r*10+j];
                float4 h = *(const float4*)&cat[(4+hsn)*320 + j*32 + c4];
                sum.x += a*h.x; sum.y += a*h.y; sum.z += a*h.z; sum.w += a*h.w;
            }
            *(float4*)&cat[m*320 + r*32 + c4] = sum;
        }
        __syncthreads();
        {
            const int col = tid & 31;
            const int s   = (tid>>5) & 1;
            const int q   = tid>>6;      // 0..3 -> 56 k (14 quads) each
            const ulonglong2* Wq = (const ulonglong2*)g_WdQ
                                 + (((s*2+layer)*56) + q*14)*32 + col;
            u64 accP[10];
            #pragma unroll
            for (int r=0;r<10;r++) accP[r]=0ull;
            #pragma unroll 2
            for (int kq=0;kq<14;kq++){
                int k = q*56 + kq*4;
                int blk = k>>5, ko = k&31;
                const float* srcp = cat + ((blk<6) ? blk : (4+s))*320 + ko;
                ulonglong2 w = Wq[kq*32];
                #pragma unroll
                for (int r=0;r<10;r++){
                    ulonglong2 a = *(const ulonglong2*)&srcp[r*32];
                    ffma2(accP[r], a.x, w.x);
                    ffma2(accP[r], a.y, w.y);
                }
            }
            #pragma unroll
            for (int r=0;r<10;r++) part[((q*2+s)*10+r)*32+col] = hadd2(accP[r]);
        }
        __syncthreads();
        for (int o=tid; o<640; o+=256){
            int s = o/320, rem = o - s*320, r = rem>>5, col = rem&31;
            float v = (s ? bnd : bpd)[layer*32+col];
            #pragma unroll
            for (int q=0;q<4;q++) v += part[((q*2+s)*10+r)*32+col];
            cat[(4+s)*320 + r*32 + col] = tanh_mufu(v);
        }
        __syncthreads();
    }

    // write z
    float* zo = g_z + (size_t)bt*PP*64;
    for (int o=tid; o<640; o+=256){
        int r = o>>6, c = o&63, s = c>>5, cc = c&31;
        zo[o] = cat[(4+s)*320 + r*32 + cc];
    }
}

// ------------------------------------------------------------------
// Kernel 2: gates_ih = z @ W_ih^T + (b_ih + b_hh)
// thread = gate g (coalesced weight loads), 16 bt-rows per block. FFMA2.
// grid: (BT/16, PP)
// ------------------------------------------------------------------
__global__ __launch_bounds__(256) void gih_kernel(
    const float* __restrict__ bih, const float* __restrict__ bhh)
{
    __shared__ __align__(16) float zs[16*64];

    const int p   = blockIdx.y;
    const int r0  = blockIdx.x * 16;
    const int g   = threadIdx.x;    // gate 0..255

    {   // one float4 per thread
        int rr = g >> 4, d4 = g & 15;
        ((float4*)zs)[g] = *(const float4*)&g_z[((size_t)(r0+rr)*10 + p)*64 + d4*4];
    }
    __syncthreads();

    const ulonglong2* Wq = (const ulonglong2*)g_WihQ + p*4096 + g;  // [iq][g] stride 256

    u64 accP[16];
    #pragma unroll
    for (int r=0;r<16;r++) accP[r]=0ull;

    #pragma unroll 4
    for (int iq=0; iq<16; iq++){
        ulonglong2 w = Wq[iq*256];
        #pragma unroll
        for (int r=0;r<16;r++){
            ulonglong2 z2 = *(const ulonglong2*)&zs[r*64 + iq*4];
            ffma2(accP[r], z2.x, w.x);
            ffma2(accP[r], z2.y, w.y);
        }
    }

    float bsum = bih[p*256+g] + bhh[p*256+g];
    #pragma unroll
    for (int r=0;r<16;r++){
        g_gih[((size_t)(r0+r)*10 + p)*256 + g] = hadd2(accP[r]) + bsum;
    }
}

// ------------------------------------------------------------------
// Kernel 3: LSTM recurrence (Round-3 version, known good).
// One block per (p, 4-game chunk). grid = PP*(BG/4) = 640.
// ------------------------------------------------------------------
__global__ __launch_bounds__(256) void lstm_kernel(
    const float* __restrict__ Whh, float* __restrict__ out)
{
    __shared__ float hs[4][64];
    __shared__ float gsm[4][256];

    const int p     = blockIdx.x >> 6;
    const int chunk = blockIdx.x & 63;
    const int b0    = chunk*4;
    const int gt    = threadIdx.x;
    const int gm    = gt >> 6;
    const int j     = gt & 63;

    float wreg[64];
    {
        const float* Wp = Whh + (size_t)p*16384 + gt*64;
        #pragma unroll
        for (int k=0;k<64;k+=4){
            float4 w4 = *(const float4*)&Wp[k];
            wreg[k+0]=w4.x; wreg[k+1]=w4.y; wreg[k+2]=w4.z; wreg[k+3]=w4.w;
        }
    }
    ((float*)hs)[gt] = 0.f;
    float creg = 0.f;
    __syncthreads();

    float pf[4];
    #pragma unroll
    for (int g4=0; g4<4; g4++)
        pf[g4] = g_gih[((size_t)(b0+g4)*64*10 + p)*256 + gt];

    for (int t=0; t<TT; t++){
        float acc0 = pf[0], acc1 = pf[1], acc2 = pf[2], acc3 = pf[3];
        #pragma unroll
        for (int k0=0;k0<64;k0+=4){
            float4 h0 = *(const float4*)&hs[0][k0];
            float4 h1 = *(const float4*)&hs[1][k0];
            float4 h2 = *(const float4*)&hs[2][k0];
            float4 h3 = *(const float4*)&hs[3][k0];
            float w0 = wreg[k0], w1 = wreg[k0+1], w2 = wreg[k0+2], w3 = wreg[k0+3];
            acc0 += w0*h0.x + w1*h0.y + w2*h0.z + w3*h0.w;
            acc1 += w0*h1.x + w1*h1.y + w2*h1.z + w3*h1.w;
            acc2 += w0*h2.x + w1*h2.y + w2*h2.z + w3*h2.w;
            acc3 += w0*h3.x + w1*h3.y + w2*h3.z + w3*h3.w;
        }
        if (t < TT-1){
            #pragma unroll
            for (int g4=0; g4<4; g4++)
                pf[g4] = g_gih[(((size_t)(b0+g4)*64 + t+1)*10 + p)*256 + gt];
        }
        gsm[0][gt] = acc0; gsm[1][gt] = acc1; gsm[2][gt] = acc2; gsm[3][gt] = acc3;
        __syncthreads();
        {
            float ig = sigmoid_fast(gsm[gm][j]);
            float fg = sigmoid_fast(gsm[gm][64+j]);
            float gg = tanh_fast   (gsm[gm][128+j]);
            float og = sigmoid_fast(gsm[gm][192+j]);
            creg = fg*creg + ig*gg;
            float h = og*tanh_fast(creg);
            hs[gm][j] = h;
            size_t bt = (size_t)(b0+gm)*64 + t;
            out[(bt*10 + p)*64 + j] = h;
        }
        __syncthreads();
    }
}

// ------------------------------------------------------------------
extern "C" void kernel_launch(void* const* d_in, const int* in_sizes, int n_in,
                              void* d_out, int out_size)
{
    const float* x    = (const float*)d_in[0];
    const float* Apos = (const float*)d_in[1];
    const float* Aneg = (const float*)d_in[2];
    const float* Wpb  = (const float*)d_in[3];
    const float* bpb  = (const float*)d_in[4];
    const float* Wnb  = (const float*)d_in[5];
    const float* bnb  = (const float*)d_in[6];
    const float* Wpd  = (const float*)d_in[7];
    const float* bpd  = (const float*)d_in[8];
    const float* Wnd  = (const float*)d_in[9];
    const float* bnd  = (const float*)d_in[10];
    const float* Wih  = (const float*)d_in[11];
    const float* Whh  = (const float*)d_in[12];
    const float* bih  = (const float*)d_in[13];
    const float* bhh  = (const float*)d_in[14];
    float* out = (float*)d_out;

    const int nW = 2*64*32 + 2*2*56*32 + PP*16*256;
    transform_weights<<<(nW + 255)/256, 256>>>(Wpb, Wnb, Wpd, Wnd, Wih);

    sgcn_kernel<<<BT, 256>>>(x, Apos, Aneg, bpb, bnb, bpd, bnd);

    dim3 gg(BT/16, PP);
    gih_kernel<<<gg, 256>>>(bih, bhh);

    lstm_kernel<<<PP*(BG/4), 256>>>(Whh, out);   // 640 blocks
}